// round 6
// baseline (speedup 1.0000x reference)
#include <cuda_runtime.h>
#include <math.h>

#define MDIM 4096
#define CDIM 1024
#define T_SEQ 2048
#define N_H 16
#define D_HEAD 64

typedef unsigned int u32;

// Scratch (device globals; allocation-free per harness rules)
__device__ u32 g_xt[MDIM * CDIM];                    // x, tf32
__device__ u32 g_wt[4][CDIM * CDIM];                 // W{q,k,v,o} transposed [n][k], tf32
__device__ u32 g_q[MDIM * CDIM];                     // tf32, pre-scaled 0.125
__device__ u32 g_k[MDIM * CDIM];                     // tf32
__device__ u32 g_vt[2 * N_H * D_HEAD * T_SEQ];       // tf32, [b,h,d,t]
__device__ u32 g_y[MDIM * CDIM];                     // tf32

// ---------------------------------------------------------------------------
// helpers
// ---------------------------------------------------------------------------
__device__ __forceinline__ u32 f2tf(float f) {
    u32 r;
    asm("cvt.rna.tf32.f32 %0, %1;" : "=r"(r) : "f"(f));
    return r;
}

__device__ __forceinline__ void mma8(float* d, const u32* a, const u32* b) {
    asm volatile(
        "mma.sync.aligned.m16n8k8.row.col.f32.tf32.tf32.f32 "
        "{%0,%1,%2,%3}, {%4,%5,%6,%7}, {%8,%9}, {%0,%1,%2,%3};"
        : "+f"(d[0]), "+f"(d[1]), "+f"(d[2]), "+f"(d[3])
        : "r"(a[0]), "r"(a[1]), "r"(a[2]), "r"(a[3]), "r"(b[0]), "r"(b[1]));
}

__device__ __forceinline__ void ldsm4(u32& r0, u32& r1, u32& r2, u32& r3, u32 addr) {
    asm volatile("ldmatrix.sync.aligned.m8n8.x4.shared.b16 {%0,%1,%2,%3}, [%4];"
                 : "=r"(r0), "=r"(r1), "=r"(r2), "=r"(r3) : "r"(addr));
}

__device__ __forceinline__ void cp16(u32 dst, const void* src) {
    asm volatile("cp.async.cg.shared.global [%0], [%1], 16;" :: "r"(dst), "l"(src));
}
#define CP_COMMIT() asm volatile("cp.async.commit_group;")
#define CP_WAIT(n)  asm volatile("cp.async.wait_group %0;" :: "n"(n))

// ---------------------------------------------------------------------------
// prep: x -> tf32; W -> transposed [n][k] tf32
// ---------------------------------------------------------------------------
__global__ __launch_bounds__(256) void prep_x_kernel(const float* __restrict__ x)
{
    const float4* src = (const float4*)x;
    uint4* dst = (uint4*)g_xt;
    const int n4 = MDIM * CDIM / 4;
    for (int i = blockIdx.x * blockDim.x + threadIdx.x; i < n4;
         i += gridDim.x * blockDim.x) {
        float4 v = src[i];
        uint4 o;
        o.x = f2tf(v.x); o.y = f2tf(v.y); o.z = f2tf(v.z); o.w = f2tf(v.w);
        dst[i] = o;
    }
}

__global__ __launch_bounds__(256) void prep_w_kernel(const float* __restrict__ Wq,
                                                     const float* __restrict__ Wk,
                                                     const float* __restrict__ Wv,
                                                     const float* __restrict__ Wo)
{
    const int z = blockIdx.z;
    const float* W = (z == 0) ? Wq : (z == 1) ? Wk : (z == 2) ? Wv : Wo;
    u32* D = g_wt[z];
    __shared__ float t[32][33];
    const int n0 = blockIdx.x * 32, k0 = blockIdx.y * 32;
    const int tx = threadIdx.x, ty = threadIdx.y;  // 32 x 8
#pragma unroll
    for (int i = 0; i < 32; i += 8)
        t[ty + i][tx] = W[(size_t)(k0 + ty + i) * CDIM + n0 + tx];  // t[k][n]
    __syncthreads();
#pragma unroll
    for (int i = 0; i < 32; i += 8)
        D[(size_t)(n0 + ty + i) * CDIM + k0 + tx] = f2tf(t[tx][ty + i]);
}

// ---------------------------------------------------------------------------
// tf32 GEMM: C[4096,1024] = A[m][k] @ Bt[n][k]^T, both tf32 in gmem.
// 128x128 tile, ktile 32, 256 thr (8 warps 4x2, warp tile 32x64).
// 2-stage cp.async double buffer; A and B both [r][k] pad-36 in smem, all
// fragments via ldmatrix.x4. OUT_MODE 0: float+bias; 1: tf32*oscale; 2: V-T.
// ---------------------------------------------------------------------------
#define AS_LD 36
#define STG (128 * AS_LD)                 // 4608 u32 per operand per stage
#define GEMM_SMEM (4 * STG * 4)           // 73728 B -> 2 CTAs/SM

template <int OUT_MODE>
__device__ __forceinline__ void gemm_core(const u32* __restrict__ A,
                                          const u32* __restrict__ Bt,
                                          const float* __restrict__ bias,
                                          void* __restrict__ Cv, float oscale)
{
    extern __shared__ u32 sm[];
    const u32 smbase = (u32)__cvta_generic_to_shared(sm);

    const int tid = threadIdx.x;
    const int lane = tid & 31;
    const int warp = tid >> 5;
    const int wm = warp >> 1;        // 0..3
    const int wn = warp & 1;         // 0..1
    const int g = lane >> 2;
    const int t = lane & 3;
    const int lrow = (lane & 7) | ((lane & 16) >> 1);
    const int lcol = (lane & 8) >> 1;

    const int row0 = blockIdx.y * 128;
    const int col0 = blockIdx.x * 128;

    // loader mapping: each thread copies 4 uint4 per operand per k-tile
    const int l_row = tid >> 1;
    const int l_kq = (tid & 1) * 16;
    const u32* Ag = A + (size_t)(row0 + l_row) * CDIM + l_kq;
    const u32* Bg = Bt + (size_t)(col0 + l_row) * CDIM + l_kq;
    const u32 sOff = (u32)(l_row * AS_LD + l_kq) * 4;

    // ldmatrix bases (words)
    const u32 a_f0 = (u32)((wm * 32 + lrow) * AS_LD + lcol);
    const u32 b_f0 = (u32)((wn * 64 + lrow) * AS_LD + lcol);

    float acc[2][8][4];
#pragma unroll
    for (int mt = 0; mt < 2; mt++)
#pragma unroll
        for (int nt = 0; nt < 8; nt++)
#pragma unroll
            for (int i = 0; i < 4; i++) acc[mt][nt][i] = 0.f;

    // buffers: [buf][A|B]: A at buf*2*STG, B at buf*2*STG + STG
    auto issue = [&](int buf, int kt) {
        const u32 sA = smbase + (u32)(buf * 2 * STG) * 4 + sOff;
        const u32 sB = sA + (u32)STG * 4;
        const u32* a = Ag + kt * 32;
        const u32* b = Bg + kt * 32;
#pragma unroll
        for (int i = 0; i < 4; i++) {
            cp16(sA + 16 * i, a + 4 * i);
            cp16(sB + 16 * i, b + 4 * i);
        }
    };

    issue(0, 0); CP_COMMIT();
    issue(1, 1); CP_COMMIT();

    for (int kt = 0; kt < 32; kt++) {
        CP_WAIT(1);
        __syncthreads();

        const int buf = kt & 1;
        const u32 abase = smbase + (u32)(buf * 2 * STG + a_f0) * 4;
        const u32 bbase = smbase + (u32)(buf * 2 * STG + STG + b_f0) * 4;
#pragma unroll
        for (int kk = 0; kk < 4; kk++) {
            u32 af[2][4];
#pragma unroll
            for (int mt = 0; mt < 2; mt++) {
                u32 r0, r1, r2, r3;
                ldsm4(r0, r1, r2, r3, abase + (u32)(mt * 16 * AS_LD + kk * 8) * 4);
                af[mt][0] = r0; af[mt][1] = r2; af[mt][2] = r1; af[mt][3] = r3;
            }
            u32 bf[8][2];
#pragma unroll
            for (int ntp = 0; ntp < 4; ntp++) {
                u32 r0, r1, r2, r3;
                ldsm4(r0, r1, r2, r3, bbase + (u32)(ntp * 16 * AS_LD + kk * 8) * 4);
                bf[2 * ntp][0] = r0; bf[2 * ntp][1] = r1;
                bf[2 * ntp + 1][0] = r2; bf[2 * ntp + 1][1] = r3;
            }
#pragma unroll
            for (int nt = 0; nt < 8; nt++)
#pragma unroll
                for (int mt = 0; mt < 2; mt++)
                    mma8(acc[mt][nt], af[mt], bf[nt]);
        }

        __syncthreads();
        if (kt + 2 < 32) issue(buf, kt + 2);
        CP_COMMIT();
    }

    // epilogue
#pragma unroll
    for (int mt = 0; mt < 2; mt++) {
#pragma unroll
        for (int nt = 0; nt < 8; nt++) {
            const int r = row0 + wm * 32 + mt * 16 + g;
            const int c = col0 + wn * 64 + nt * 8 + t * 2;
            if (OUT_MODE == 0) {
                float* C = (float*)Cv;
                const float b0 = bias[c], b1 = bias[c + 1];
                *(float2*)(C + (size_t)r * CDIM + c) =
                    make_float2(acc[mt][nt][0] + b0, acc[mt][nt][1] + b1);
                *(float2*)(C + (size_t)(r + 8) * CDIM + c) =
                    make_float2(acc[mt][nt][2] + b0, acc[mt][nt][3] + b1);
            } else if (OUT_MODE == 1) {
                u32* C = (u32*)Cv;
                uint2 v0, v1;
                v0.x = f2tf(acc[mt][nt][0] * oscale);
                v0.y = f2tf(acc[mt][nt][1] * oscale);
                v1.x = f2tf(acc[mt][nt][2] * oscale);
                v1.y = f2tf(acc[mt][nt][3] * oscale);
                *(uint2*)(C + (size_t)r * CDIM + c) = v0;
                *(uint2*)(C + (size_t)(r + 8) * CDIM + c) = v1;
            } else {
                // V transposed: C[b,h,d,t], r -> (b,t), c -> (h,d)
                u32* C = (u32*)Cv;
                const int bb = r >> 11;
                const int tt = r & 2047;
                const int hh = c >> 6;
                const int dd = c & 63;
                u32* base = C + (size_t)((bb * N_H + hh) * D_HEAD + dd) * T_SEQ;
                base[tt] = f2tf(acc[mt][nt][0]);
                base[T_SEQ + tt] = f2tf(acc[mt][nt][1]);
                base[tt + 8] = f2tf(acc[mt][nt][2]);
                base[T_SEQ + tt + 8] = f2tf(acc[mt][nt][3]);
            }
        }
    }
}

__global__ __launch_bounds__(256, 2) void qkv_gemm_kernel()
{
    const int z = blockIdx.z;
    if (z == 0) gemm_core<1>(g_xt, g_wt[0], nullptr, g_q, 0.125f);
    else if (z == 1) gemm_core<1>(g_xt, g_wt[1], nullptr, g_k, 1.0f);
    else gemm_core<2>(g_xt, g_wt[2], nullptr, g_vt, 1.0f);
}

__global__ __launch_bounds__(256, 2) void out_gemm_kernel(const float* __restrict__ bo,
                                                          float* __restrict__ out)
{
    gemm_core<0>(g_y, g_wt[3], bo, out, 1.0f);
}

// ---------------------------------------------------------------------------
// Flash attention, tf32, causal (unchanged from R4/R5 proven version).
// 256 thr (8 warps x 16 q-rows = 128 queries). KV tile 64, 2-stage cp.async.
// K [kv][d] and Vt [d][kv] both n-major -> all mma B-fragments via ldmatrix.
// grid: (T/128, H, B), reversed x order.
// ---------------------------------------------------------------------------
#define FKV_LD 68
#define FKV_SZ (64 * FKV_LD)   // 4352
#define FP_LD 68
#define FP_SZ (16 * FP_LD)     // 1088
#define VT_OFF (2 * FKV_SZ)
#define PS_OFF (4 * FKV_SZ)
#define FLASH_SMEM_BYTES ((4 * FKV_SZ + 8 * FP_SZ) * 4)   // 104448 B

__device__ __forceinline__ void flash_issue(u32 smbase, const u32* Kg, const u32* Vtg,
                                            int j0, int buf, int tid)
{
    const int r = tid >> 2;
    const int cs = (tid & 3) * 16;
    const u32* ks = Kg + (size_t)(j0 + r) * CDIM + cs;
    const u32* vs = Vtg + (size_t)r * T_SEQ + j0 + cs;
    const u32 kd = smbase + (u32)(buf * FKV_SZ + r * FKV_LD + cs) * 4;
    const u32 vd = smbase + (u32)(VT_OFF + buf * FKV_SZ + r * FKV_LD + cs) * 4;
#pragma unroll
    for (int i = 0; i < 4; i++) {
        cp16(kd + 16 * i, ks + 4 * i);
        cp16(vd + 16 * i, vs + 4 * i);
    }
}

__global__ __launch_bounds__(256) void flash_tf32_kernel()
{
    extern __shared__ u32 sm[];
    const u32 smbase = (u32)__cvta_generic_to_shared(sm);

    const int tid = threadIdx.x;
    const int lane = tid & 31;
    const int warp = tid >> 5;
    const int g = lane >> 2;
    const int t4 = lane & 3;
    const int lrow = (lane & 7) | ((lane & 16) >> 1);
    const int lcol = (lane & 8) >> 1;
    const int b = blockIdx.z;
    const int h = blockIdx.y;
    const int qb = gridDim.x - 1 - blockIdx.x;
    const int q0 = qb * 128;
    const int qw = q0 + warp * 16;

    const u32* Kg = g_k + (size_t)(b * T_SEQ) * CDIM + h * D_HEAD;
    const u32* Vtg = g_vt + (size_t)((b * N_H + h) * D_HEAD) * T_SEQ;

    const u32* Qg = g_q + (size_t)(b * T_SEQ + qw) * CDIM + h * D_HEAD;
    u32 qa[8][4];
#pragma unroll
    for (int kc = 0; kc < 8; kc++) {
        qa[kc][0] = Qg[(size_t)g * CDIM + kc * 8 + t4];
        qa[kc][1] = Qg[(size_t)(g + 8) * CDIM + kc * 8 + t4];
        qa[kc][2] = Qg[(size_t)g * CDIM + kc * 8 + t4 + 4];
        qa[kc][3] = Qg[(size_t)(g + 8) * CDIM + kc * 8 + t4 + 4];
    }

    float o[8][4];
#pragma unroll
    for (int nt = 0; nt < 8; nt++)
#pragma unroll
        for (int i = 0; i < 4; i++) o[nt][i] = 0.f;
    float m0 = -INFINITY, m1 = -INFINITY, l0 = 0.f, l1 = 0.f;

    const int ntiles = 2 * (qb + 1);
    const u32 p_off = (u32)(PS_OFF + warp * FP_SZ);
    u32* Pw = sm + p_off;

    flash_issue(smbase, Kg, Vtg, 0, 0, tid);
    CP_COMMIT();

#pragma unroll 1
    for (int tile = 0; tile < ntiles; tile++) {
        const int j0 = tile * 64;
        const int buf = tile & 1;
        if (tile + 1 < ntiles)
            flash_issue(smbase, Kg, Vtg, j0 + 64, (tile + 1) & 1, tid);
        CP_COMMIT();
        CP_WAIT(1);
        __syncthreads();

        if (j0 <= qw + 15) {
            float s[8][4];
#pragma unroll
            for (int nt = 0; nt < 8; nt++)
#pragma unroll
                for (int i = 0; i < 4; i++) s[nt][i] = 0.f;

            const u32 kbase = smbase + (u32)(buf * FKV_SZ + lrow * FKV_LD + lcol) * 4;
#pragma unroll
            for (int kc = 0; kc < 8; kc++) {
                u32 bf[8][2];
#pragma unroll
                for (int ntp = 0; ntp < 4; ntp++) {
                    u32 r0, r1, r2, r3;
                    ldsm4(r0, r1, r2, r3, kbase + (u32)(ntp * 16 * FKV_LD + kc * 8) * 4);
                    bf[2 * ntp][0] = r0; bf[2 * ntp][1] = r1;
                    bf[2 * ntp + 1][0] = r2; bf[2 * ntp + 1][1] = r3;
                }
#pragma unroll
                for (int nt = 0; nt < 8; nt++)
                    mma8(s[nt], qa[kc], bf[nt]);
            }

            if (j0 + 63 > qw) {
#pragma unroll
                for (int nt = 0; nt < 8; nt++) {
                    const int cb = j0 + nt * 8 + 2 * t4;
                    if (cb     > qw + g)     s[nt][0] = -INFINITY;
                    if (cb + 1 > qw + g)     s[nt][1] = -INFINITY;
                    if (cb     > qw + g + 8) s[nt][2] = -INFINITY;
                    if (cb + 1 > qw + g + 8) s[nt][3] = -INFINITY;
                }
            }

            float mx0 = -INFINITY, mx1 = -INFINITY;
#pragma unroll
            for (int nt = 0; nt < 8; nt++) {
                mx0 = fmaxf(mx0, fmaxf(s[nt][0], s[nt][1]));
                mx1 = fmaxf(mx1, fmaxf(s[nt][2], s[nt][3]));
            }
            mx0 = fmaxf(mx0, __shfl_xor_sync(0xffffffffu, mx0, 1));
            mx0 = fmaxf(mx0, __shfl_xor_sync(0xffffffffu, mx0, 2));
            mx1 = fmaxf(mx1, __shfl_xor_sync(0xffffffffu, mx1, 1));
            mx1 = fmaxf(mx1, __shfl_xor_sync(0xffffffffu, mx1, 2));

            const float mn0 = fmaxf(m0, mx0);
            const float mn1 = fmaxf(m1, mx1);
            const float cr0 = __expf(m0 - mn0);
            const float cr1 = __expf(m1 - mn1);
            float sum0 = 0.f, sum1 = 0.f;
#pragma unroll
            for (int nt = 0; nt < 8; nt++) {
                s[nt][0] = __expf(s[nt][0] - mn0);
                s[nt][1] = __expf(s[nt][1] - mn0);
                s[nt][2] = __expf(s[nt][2] - mn1);
                s[nt][3] = __expf(s[nt][3] - mn1);
                sum0 += s[nt][0] + s[nt][1];
                sum1 += s[nt][2] + s[nt][3];
            }
            sum0 += __shfl_xor_sync(0xffffffffu, sum0, 1);
            sum0 += __shfl_xor_sync(0xffffffffu, sum0, 2);
            sum1 += __shfl_xor_sync(0xffffffffu, sum1, 1);
            sum1 += __shfl_xor_sync(0xffffffffu, sum1, 2);
            l0 = l0 * cr0 + sum0;
            l1 = l1 * cr1 + sum1;
            m0 = mn0;
            m1 = mn1;
#pragma unroll
            for (int nt = 0; nt < 8; nt++) {
                o[nt][0] *= cr0;
                o[nt][1] *= cr0;
                o[nt][2] *= cr1;
                o[nt][3] *= cr1;
            }

#pragma unroll
            for (int nt = 0; nt < 8; nt++) {
                uint2 v0, v1;
                v0.x = f2tf(s[nt][0]); v0.y = f2tf(s[nt][1]);
                v1.x = f2tf(s[nt][2]); v1.y = f2tf(s[nt][3]);
                *(uint2*)(Pw + g * FP_LD + nt * 8 + 2 * t4) = v0;
                *(uint2*)(Pw + (g + 8) * FP_LD + nt * 8 + 2 * t4) = v1;
            }
            __syncwarp();

            const u32 pbase = smbase + (u32)(p_off + lrow * FP_LD + lcol) * 4;
            const u32 vbase = smbase +
                (u32)(VT_OFF + buf * FKV_SZ + lrow * FKV_LD + lcol) * 4;
#pragma unroll
            for (int kc = 0; kc < 8; kc++) {
                u32 r0, r1, r2, r3;
                ldsm4(r0, r1, r2, r3, pbase + (u32)(kc * 8) * 4);
                u32 af[4] = {r0, r2, r1, r3};
                u32 bf[8][2];
#pragma unroll
                for (int ntp = 0; ntp < 4; ntp++) {
                    u32 q0r, q1r, q2r, q3r;
                    ldsm4(q0r, q1r, q2r, q3r, vbase + (u32)(ntp * 16 * FKV_LD + kc * 8) * 4);
                    bf[2 * ntp][0] = q0r; bf[2 * ntp][1] = q1r;
                    bf[2 * ntp + 1][0] = q2r; bf[2 * ntp + 1][1] = q3r;
                }
#pragma unroll
                for (int nt = 0; nt < 8; nt++)
                    mma8(o[nt], af, bf[nt]);
            }
            __syncwarp();
        }
        __syncthreads();
    }

    const float inv0 = 1.f / l0;
    const float inv1 = 1.f / l1;
    u32* Yg = g_y + (size_t)(b * T_SEQ + qw) * CDIM + h * D_HEAD;
#pragma unroll
    for (int nt = 0; nt < 8; nt++) {
        const int c = nt * 8 + 2 * t4;
        uint2 v0, v1;
        v0.x = f2tf(o[nt][0] * inv0); v0.y = f2tf(o[nt][1] * inv0);
        v1.x = f2tf(o[nt][2] * inv1); v1.y = f2tf(o[nt][3] * inv1);
        *(uint2*)(Yg + (size_t)g * CDIM + c) = v0;
        *(uint2*)(Yg + (size_t)(g + 8) * CDIM + c) = v1;
    }
}

// ---------------------------------------------------------------------------
extern "C" void kernel_launch(void* const* d_in, const int* in_sizes, int n_in,
                              void* d_out, int out_size)
{
    const float* x  = (const float*)d_in[0];
    const float* Wq = (const float*)d_in[1];
    const float* Wk = (const float*)d_in[2];
    const float* Wv = (const float*)d_in[3];
    const float* Wo = (const float*)d_in[4];
    const float* bo = (const float*)d_in[5];
    float* out = (float*)d_out;
    (void)in_sizes; (void)n_in; (void)out_size;

    cudaFuncSetAttribute(qkv_gemm_kernel, cudaFuncAttributeMaxDynamicSharedMemorySize, GEMM_SMEM);
    cudaFuncSetAttribute(out_gemm_kernel, cudaFuncAttributeMaxDynamicSharedMemorySize, GEMM_SMEM);
    cudaFuncSetAttribute(flash_tf32_kernel, cudaFuncAttributeMaxDynamicSharedMemorySize, FLASH_SMEM_BYTES);

    prep_x_kernel<<<1024, 256>>>(x);
    prep_w_kernel<<<dim3(32, 32, 4), dim3(32, 8)>>>(Wq, Wk, Wv, Wo);

    dim3 qkv_grid(CDIM / 128, MDIM / 128, 3);
    qkv_gemm_kernel<<<qkv_grid, 256, GEMM_SMEM>>>();

    dim3 attn_grid(T_SEQ / 128, N_H, 2);
    flash_tf32_kernel<<<attn_grid, 256, FLASH_SMEM_BYTES>>>();

    dim3 out_grid(CDIM / 128, MDIM / 128);
    out_gemm_kernel<<<out_grid, 256, GEMM_SMEM>>>(bo, out);
}

// round 8
// speedup vs baseline: 1.0966x; 1.0966x over previous
#include <cuda_runtime.h>
#include <math.h>

#define MDIM 4096
#define CDIM 1024
#define T_SEQ 2048
#define N_H 16
#define D_HEAD 64

typedef unsigned int u32;

// Scratch (device globals; allocation-free per harness rules)
__device__ u32 g_xt[MDIM * CDIM];                    // x, tf32
__device__ u32 g_wt[4][CDIM * CDIM];                 // W{q,k,v,o} transposed [n][k], tf32
__device__ u32 g_q[MDIM * CDIM];                     // tf32, pre-scaled 0.125
__device__ u32 g_k[MDIM * CDIM];                     // tf32
__device__ u32 g_vt[2 * N_H * D_HEAD * T_SEQ];       // tf32, [b,h,d,t]
__device__ u32 g_y[MDIM * CDIM];                     // tf32

// ---------------------------------------------------------------------------
// helpers
// ---------------------------------------------------------------------------
__device__ __forceinline__ u32 f2tf(float f) {
    u32 r;
    asm("cvt.rna.tf32.f32 %0, %1;" : "=r"(r) : "f"(f));
    return r;
}

__device__ __forceinline__ void mma8(float* d, const u32* a, const u32* b) {
    asm volatile(
        "mma.sync.aligned.m16n8k8.row.col.f32.tf32.tf32.f32 "
        "{%0,%1,%2,%3}, {%4,%5,%6,%7}, {%8,%9}, {%0,%1,%2,%3};"
        : "+f"(d[0]), "+f"(d[1]), "+f"(d[2]), "+f"(d[3])
        : "r"(a[0]), "r"(a[1]), "r"(a[2]), "r"(a[3]), "r"(b[0]), "r"(b[1]));
}

__device__ __forceinline__ void ldsm4(u32& r0, u32& r1, u32& r2, u32& r3, u32 addr) {
    asm volatile("ldmatrix.sync.aligned.m8n8.x4.shared.b16 {%0,%1,%2,%3}, [%4];"
                 : "=r"(r0), "=r"(r1), "=r"(r2), "=r"(r3) : "r"(addr));
}

__device__ __forceinline__ void cp16(u32 dst, const void* src) {
    asm volatile("cp.async.cg.shared.global [%0], [%1], 16;" :: "r"(dst), "l"(src));
}
#define CP_COMMIT() asm volatile("cp.async.commit_group;")
#define CP_WAIT(n)  asm volatile("cp.async.wait_group %0;" :: "n"(n))

// ---------------------------------------------------------------------------
// prep: x -> tf32; W -> transposed [n][k] tf32 (verified R3/R6)
// ---------------------------------------------------------------------------
__global__ __launch_bounds__(256) void prep_x_kernel(const float* __restrict__ x)
{
    const float4* src = (const float4*)x;
    uint4* dst = (uint4*)g_xt;
    const int n4 = MDIM * CDIM / 4;
    for (int i = blockIdx.x * blockDim.x + threadIdx.x; i < n4;
         i += gridDim.x * blockDim.x) {
        float4 v = src[i];
        uint4 o;
        o.x = f2tf(v.x); o.y = f2tf(v.y); o.z = f2tf(v.z); o.w = f2tf(v.w);
        dst[i] = o;
    }
}

__global__ __launch_bounds__(256) void prep_w_kernel(const float* __restrict__ Wq,
                                                     const float* __restrict__ Wk,
                                                     const float* __restrict__ Wv,
                                                     const float* __restrict__ Wo)
{
    const int z = blockIdx.z;
    const float* W = (z == 0) ? Wq : (z == 1) ? Wk : (z == 2) ? Wv : Wo;
    u32* D = g_wt[z];
    __shared__ float t[32][33];
    const int n0 = blockIdx.x * 32, k0 = blockIdx.y * 32;
    const int tx = threadIdx.x, ty = threadIdx.y;  // 32 x 8
#pragma unroll
    for (int i = 0; i < 32; i += 8)
        t[ty + i][tx] = W[(size_t)(k0 + ty + i) * CDIM + n0 + tx];
    __syncthreads();
#pragma unroll
    for (int i = 0; i < 32; i += 8)
        D[(size_t)(n0 + ty + i) * CDIM + k0 + tx] = f2tf(t[tx][ty + i]);
}

// ---------------------------------------------------------------------------
// tf32 GEMM: C[4096,1024] = A[m][k] @ Bt[n][k]^T, both tf32 u32 in gmem.
// R4-proven skeleton: reg-staged LDG, ping-pong smem, single sync per k-tile.
// Both operands in smem as [row][k] pad-36; ALL fragments via ldmatrix.x4.
// 128x128 tile, ktile 32, 256 thr (8 warps 4x2, warp tile 32x64).
// OUT_MODE 0: float+bias; 1: tf32*oscale; 2: V-transposed scatter.
// ---------------------------------------------------------------------------
#define AS_LD 36
#define AS_SZ (128 * AS_LD)                 // 4608 u32
#define GEMM_SMEM (4 * AS_SZ * 4)           // A[2] + B[2] = 73728 B

template <int OUT_MODE>
__device__ __forceinline__ void gemm_core(const u32* __restrict__ A,
                                          const u32* __restrict__ Bt,
                                          const float* __restrict__ bias,
                                          void* __restrict__ Cv, float oscale)
{
    extern __shared__ u32 sm[];
    u32* As = sm;                 // [2][AS_SZ]
    u32* Bs = sm + 2 * AS_SZ;     // [2][AS_SZ]
    const u32 smbase = (u32)__cvta_generic_to_shared(sm);

    const int tid = threadIdx.x;
    const int lane = tid & 31;
    const int warp = tid >> 5;
    const int wm = warp >> 1;
    const int wn = warp & 1;
    const int g = lane >> 2;
    const int t = lane & 3;
    const int lrow = (lane & 7) | ((lane & 16) >> 1);
    const int lcol = (lane & 8) >> 1;

    const int row0 = blockIdx.y * 128;
    const int col0 = blockIdx.x * 128;

    // loader mapping (same for A and B): row = tid>>1, kq = (tid&1)*16
    const int l_row = tid >> 1;
    const int l_kq = (tid & 1) * 16;
    const u32* Ag = A + (size_t)(row0 + l_row) * CDIM + l_kq;
    const u32* Bg = Bt + (size_t)(col0 + l_row) * CDIM + l_kq;

    // ldmatrix fragment bases (words, within one buffer)
    const u32 a_f0 = (u32)((wm * 32 + lrow) * AS_LD + lcol);
    const u32 b_f0 = (u32)((wn * 64 + lrow) * AS_LD + lcol);

    uint4 ar[4], br[4];

    float acc[2][8][4];
#pragma unroll
    for (int mt = 0; mt < 2; mt++)
#pragma unroll
        for (int nt = 0; nt < 8; nt++)
#pragma unroll
            for (int i = 0; i < 4; i++) acc[mt][nt][i] = 0.f;

    // prologue: tile 0
#pragma unroll
    for (int i = 0; i < 4; i++) {
        ar[i] = *(const uint4*)(Ag + 4 * i);
        br[i] = *(const uint4*)(Bg + 4 * i);
    }
    {
        u32* ap = As + l_row * AS_LD + l_kq;
        u32* bp = Bs + l_row * AS_LD + l_kq;
#pragma unroll
        for (int i = 0; i < 4; i++) {
            *(uint4*)(ap + 4 * i) = ar[i];
            *(uint4*)(bp + 4 * i) = br[i];
        }
    }
    __syncthreads();

    for (int kt = 0; kt < 32; kt++) {
        const int cur = kt & 1;
        if (kt < 31) {
            const int k0 = (kt + 1) * 32;
#pragma unroll
            for (int i = 0; i < 4; i++) {
                ar[i] = *(const uint4*)(Ag + k0 + 4 * i);
                br[i] = *(const uint4*)(Bg + k0 + 4 * i);
            }
        }
        const u32 abase = smbase + (u32)(cur * AS_SZ + a_f0) * 4;
        const u32 bbase = smbase + (u32)((2 + cur) * AS_SZ + b_f0) * 4;
#pragma unroll
        for (int kk = 0; kk < 4; kk++) {
            u32 af[2][4];
#pragma unroll
            for (int mt = 0; mt < 2; mt++) {
                u32 r0, r1, r2, r3;
                ldsm4(r0, r1, r2, r3, abase + (u32)(mt * 16 * AS_LD + kk * 8) * 4);
                af[mt][0] = r0; af[mt][1] = r2; af[mt][2] = r1; af[mt][3] = r3;
            }
            u32 bf[8][2];
#pragma unroll
            for (int ntp = 0; ntp < 4; ntp++) {
                u32 r0, r1, r2, r3;
                ldsm4(r0, r1, r2, r3, bbase + (u32)(ntp * 16 * AS_LD + kk * 8) * 4);
                bf[2 * ntp][0] = r0; bf[2 * ntp][1] = r1;
                bf[2 * ntp + 1][0] = r2; bf[2 * ntp + 1][1] = r3;
            }
#pragma unroll
            for (int nt = 0; nt < 8; nt++)
#pragma unroll
                for (int mt = 0; mt < 2; mt++)
                    mma8(acc[mt][nt], af[mt], bf[nt]);
        }
        if (kt < 31) {
            const int nbuf = (kt + 1) & 1;
            u32* ap = As + nbuf * AS_SZ + l_row * AS_LD + l_kq;
            u32* bp = Bs + nbuf * AS_SZ + l_row * AS_LD + l_kq;
#pragma unroll
            for (int i = 0; i < 4; i++) {
                *(uint4*)(ap + 4 * i) = ar[i];
                *(uint4*)(bp + 4 * i) = br[i];
            }
            __syncthreads();
        }
    }

    // epilogue (R4-verified mapping)
#pragma unroll
    for (int mt = 0; mt < 2; mt++) {
#pragma unroll
        for (int nt = 0; nt < 8; nt++) {
            const int r = row0 + wm * 32 + mt * 16 + g;
            const int c = col0 + wn * 64 + nt * 8 + t * 2;
            if (OUT_MODE == 0) {
                float* C = (float*)Cv;
                const float b0 = bias[c], b1 = bias[c + 1];
                *(float2*)(C + (size_t)r * CDIM + c) =
                    make_float2(acc[mt][nt][0] + b0, acc[mt][nt][1] + b1);
                *(float2*)(C + (size_t)(r + 8) * CDIM + c) =
                    make_float2(acc[mt][nt][2] + b0, acc[mt][nt][3] + b1);
            } else if (OUT_MODE == 1) {
                u32* C = (u32*)Cv;
                uint2 v0, v1;
                v0.x = f2tf(acc[mt][nt][0] * oscale);
                v0.y = f2tf(acc[mt][nt][1] * oscale);
                v1.x = f2tf(acc[mt][nt][2] * oscale);
                v1.y = f2tf(acc[mt][nt][3] * oscale);
                *(uint2*)(C + (size_t)r * CDIM + c) = v0;
                *(uint2*)(C + (size_t)(r + 8) * CDIM + c) = v1;
            } else {
                // V transposed: C[b,h,d,t], r -> (b,t), c -> (h,d)
                u32* C = (u32*)Cv;
                const int bb = r >> 11;
                const int tt = r & 2047;
                const int hh = c >> 6;
                const int dd = c & 63;
                u32* base = C + (size_t)((bb * N_H + hh) * D_HEAD + dd) * T_SEQ;
                base[tt] = f2tf(acc[mt][nt][0]);
                base[T_SEQ + tt] = f2tf(acc[mt][nt][1]);
                base[tt + 8] = f2tf(acc[mt][nt][2]);
                base[T_SEQ + tt + 8] = f2tf(acc[mt][nt][3]);
            }
        }
    }
}

__global__ __launch_bounds__(256) void qkv_gemm_kernel()
{
    const int z = blockIdx.z;
    if (z == 0) gemm_core<1>(g_xt, g_wt[0], nullptr, g_q, 0.125f);
    else if (z == 1) gemm_core<1>(g_xt, g_wt[1], nullptr, g_k, 1.0f);
    else gemm_core<2>(g_xt, g_wt[2], nullptr, g_vt, 1.0f);
}

__global__ __launch_bounds__(256) void out_gemm_kernel(const float* __restrict__ bo,
                                                       float* __restrict__ out)
{
    gemm_core<0>(g_y, g_wt[3], bo, out, 1.0f);
}

// ---------------------------------------------------------------------------
// Flash attention, tf32, causal — R4 proven version, unchanged.
// ---------------------------------------------------------------------------
#define FKV_LD 68
#define FKV_SZ (64 * FKV_LD)
#define FP_LD 68
#define FP_SZ (16 * FP_LD)
#define VT_OFF (2 * FKV_SZ)
#define PS_OFF (4 * FKV_SZ)
#define FLASH_SMEM_BYTES ((4 * FKV_SZ + 8 * FP_SZ) * 4)

__device__ __forceinline__ void flash_issue(u32 smbase, const u32* Kg, const u32* Vtg,
                                            int j0, int buf, int tid)
{
    const int r = tid >> 2;
    const int cs = (tid & 3) * 16;
    const u32* ks = Kg + (size_t)(j0 + r) * CDIM + cs;
    const u32* vs = Vtg + (size_t)r * T_SEQ + j0 + cs;
    const u32 kd = smbase + (u32)(buf * FKV_SZ + r * FKV_LD + cs) * 4;
    const u32 vd = smbase + (u32)(VT_OFF + buf * FKV_SZ + r * FKV_LD + cs) * 4;
#pragma unroll
    for (int i = 0; i < 4; i++) {
        cp16(kd + 16 * i, ks + 4 * i);
        cp16(vd + 16 * i, vs + 4 * i);
    }
}

__global__ __launch_bounds__(256) void flash_tf32_kernel()
{
    extern __shared__ u32 sm[];
    const u32 smbase = (u32)__cvta_generic_to_shared(sm);

    const int tid = threadIdx.x;
    const int lane = tid & 31;
    const int warp = tid >> 5;
    const int g = lane >> 2;
    const int t4 = lane & 3;
    const int lrow = (lane & 7) | ((lane & 16) >> 1);
    const int lcol = (lane & 8) >> 1;
    const int b = blockIdx.z;
    const int h = blockIdx.y;
    const int qb = gridDim.x - 1 - blockIdx.x;
    const int q0 = qb * 128;
    const int qw = q0 + warp * 16;

    const u32* Kg = g_k + (size_t)(b * T_SEQ) * CDIM + h * D_HEAD;
    const u32* Vtg = g_vt + (size_t)((b * N_H + h) * D_HEAD) * T_SEQ;

    const u32* Qg = g_q + (size_t)(b * T_SEQ + qw) * CDIM + h * D_HEAD;
    u32 qa[8][4];
#pragma unroll
    for (int kc = 0; kc < 8; kc++) {
        qa[kc][0] = Qg[(size_t)g * CDIM + kc * 8 + t4];
        qa[kc][1] = Qg[(size_t)(g + 8) * CDIM + kc * 8 + t4];
        qa[kc][2] = Qg[(size_t)g * CDIM + kc * 8 + t4 + 4];
        qa[kc][3] = Qg[(size_t)(g + 8) * CDIM + kc * 8 + t4 + 4];
    }

    float o[8][4];
#pragma unroll
    for (int nt = 0; nt < 8; nt++)
#pragma unroll
        for (int i = 0; i < 4; i++) o[nt][i] = 0.f;
    float m0 = -INFINITY, m1 = -INFINITY, l0 = 0.f, l1 = 0.f;

    const int ntiles = 2 * (qb + 1);
    const u32 p_off = (u32)(PS_OFF + warp * FP_SZ);
    u32* Pw = sm + p_off;

    flash_issue(smbase, Kg, Vtg, 0, 0, tid);
    CP_COMMIT();

#pragma unroll 1
    for (int tile = 0; tile < ntiles; tile++) {
        const int j0 = tile * 64;
        const int buf = tile & 1;
        if (tile + 1 < ntiles)
            flash_issue(smbase, Kg, Vtg, j0 + 64, (tile + 1) & 1, tid);
        CP_COMMIT();
        CP_WAIT(1);
        __syncthreads();

        if (j0 <= qw + 15) {
            float s[8][4];
#pragma unroll
            for (int nt = 0; nt < 8; nt++)
#pragma unroll
                for (int i = 0; i < 4; i++) s[nt][i] = 0.f;

            const u32 kbase = smbase + (u32)(buf * FKV_SZ + lrow * FKV_LD + lcol) * 4;
#pragma unroll
            for (int kc = 0; kc < 8; kc++) {
                u32 bf[8][2];
#pragma unroll
                for (int ntp = 0; ntp < 4; ntp++) {
                    u32 r0, r1, r2, r3;
                    ldsm4(r0, r1, r2, r3, kbase + (u32)(ntp * 16 * FKV_LD + kc * 8) * 4);
                    bf[2 * ntp][0] = r0; bf[2 * ntp][1] = r1;
                    bf[2 * ntp + 1][0] = r2; bf[2 * ntp + 1][1] = r3;
                }
#pragma unroll
                for (int nt = 0; nt < 8; nt++)
                    mma8(s[nt], qa[kc], bf[nt]);
            }

            if (j0 + 63 > qw) {
#pragma unroll
                for (int nt = 0; nt < 8; nt++) {
                    const int cb = j0 + nt * 8 + 2 * t4;
                    if (cb     > qw + g)     s[nt][0] = -INFINITY;
                    if (cb + 1 > qw + g)     s[nt][1] = -INFINITY;
                    if (cb     > qw + g + 8) s[nt][2] = -INFINITY;
                    if (cb + 1 > qw + g + 8) s[nt][3] = -INFINITY;
                }
            }

            float mx0 = -INFINITY, mx1 = -INFINITY;
#pragma unroll
            for (int nt = 0; nt < 8; nt++) {
                mx0 = fmaxf(mx0, fmaxf(s[nt][0], s[nt][1]));
                mx1 = fmaxf(mx1, fmaxf(s[nt][2], s[nt][3]));
            }
            mx0 = fmaxf(mx0, __shfl_xor_sync(0xffffffffu, mx0, 1));
            mx0 = fmaxf(mx0, __shfl_xor_sync(0xffffffffu, mx0, 2));
            mx1 = fmaxf(mx1, __shfl_xor_sync(0xffffffffu, mx1, 1));
            mx1 = fmaxf(mx1, __shfl_xor_sync(0xffffffffu, mx1, 2));

            const float mn0 = fmaxf(m0, mx0);
            const float mn1 = fmaxf(m1, mx1);
            const float cr0 = __expf(m0 - mn0);
            const float cr1 = __expf(m1 - mn1);
            float sum0 = 0.f, sum1 = 0.f;
#pragma unroll
            for (int nt = 0; nt < 8; nt++) {
                s[nt][0] = __expf(s[nt][0] - mn0);
                s[nt][1] = __expf(s[nt][1] - mn0);
                s[nt][2] = __expf(s[nt][2] - mn1);
                s[nt][3] = __expf(s[nt][3] - mn1);
                sum0 += s[nt][0] + s[nt][1];
                sum1 += s[nt][2] + s[nt][3];
            }
            sum0 += __shfl_xor_sync(0xffffffffu, sum0, 1);
            sum0 += __shfl_xor_sync(0xffffffffu, sum0, 2);
            sum1 += __shfl_xor_sync(0xffffffffu, sum1, 1);
            sum1 += __shfl_xor_sync(0xffffffffu, sum1, 2);
            l0 = l0 * cr0 + sum0;
            l1 = l1 * cr1 + sum1;
            m0 = mn0;
            m1 = mn1;
#pragma unroll
            for (int nt = 0; nt < 8; nt++) {
                o[nt][0] *= cr0;
                o[nt][1] *= cr0;
                o[nt][2] *= cr1;
                o[nt][3] *= cr1;
            }

#pragma unroll
            for (int nt = 0; nt < 8; nt++) {
                uint2 v0, v1;
                v0.x = f2tf(s[nt][0]); v0.y = f2tf(s[nt][1]);
                v1.x = f2tf(s[nt][2]); v1.y = f2tf(s[nt][3]);
                *(uint2*)(Pw + g * FP_LD + nt * 8 + 2 * t4) = v0;
                *(uint2*)(Pw + (g + 8) * FP_LD + nt * 8 + 2 * t4) = v1;
            }
            __syncwarp();

            const u32 pbase = smbase + (u32)(p_off + lrow * FP_LD + lcol) * 4;
            const u32 vbase = smbase +
                (u32)(VT_OFF + buf * FKV_SZ + lrow * FKV_LD + lcol) * 4;
#pragma unroll
            for (int kc = 0; kc < 8; kc++) {
                u32 r0, r1, r2, r3;
                ldsm4(r0, r1, r2, r3, pbase + (u32)(kc * 8) * 4);
                u32 af[4] = {r0, r2, r1, r3};
                u32 bf[8][2];
#pragma unroll
                for (int ntp = 0; ntp < 4; ntp++) {
                    u32 q0r, q1r, q2r, q3r;
                    ldsm4(q0r, q1r, q2r, q3r, vbase + (u32)(ntp * 16 * FKV_LD + kc * 8) * 4);
                    bf[2 * ntp][0] = q0r; bf[2 * ntp][1] = q1r;
                    bf[2 * ntp + 1][0] = q2r; bf[2 * ntp + 1][1] = q3r;
                }
#pragma unroll
                for (int nt = 0; nt < 8; nt++)
                    mma8(o[nt], af, bf[nt]);
            }
            __syncwarp();
        }
        __syncthreads();
    }

    const float inv0 = 1.f / l0;
    const float inv1 = 1.f / l1;
    u32* Yg = g_y + (size_t)(b * T_SEQ + qw) * CDIM + h * D_HEAD;
#pragma unroll
    for (int nt = 0; nt < 8; nt++) {
        const int c = nt * 8 + 2 * t4;
        uint2 v0, v1;
        v0.x = f2tf(o[nt][0] * inv0); v0.y = f2tf(o[nt][1] * inv0);
        v1.x = f2tf(o[nt][2] * inv1); v1.y = f2tf(o[nt][3] * inv1);
        *(uint2*)(Yg + (size_t)g * CDIM + c) = v0;
        *(uint2*)(Yg + (size_t)(g + 8) * CDIM + c) = v1;
    }
}

// ---------------------------------------------------------------------------
extern "C" void kernel_launch(void* const* d_in, const int* in_sizes, int n_in,
                              void* d_out, int out_size)
{
    const float* x  = (const float*)d_in[0];
    const float* Wq = (const float*)d_in[1];
    const float* Wk = (const float*)d_in[2];
    const float* Wv = (const float*)d_in[3];
    const float* Wo = (const float*)d_in[4];
    const float* bo = (const float*)d_in[5];
    float* out = (float*)d_out;
    (void)in_sizes; (void)n_in; (void)out_size;

    cudaFuncSetAttribute(qkv_gemm_kernel, cudaFuncAttributeMaxDynamicSharedMemorySize, GEMM_SMEM);
    cudaFuncSetAttribute(out_gemm_kernel, cudaFuncAttributeMaxDynamicSharedMemorySize, GEMM_SMEM);
    cudaFuncSetAttribute(flash_tf32_kernel, cudaFuncAttributeMaxDynamicSharedMemorySize, FLASH_SMEM_BYTES);

    prep_x_kernel<<<1024, 256>>>(x);
    prep_w_kernel<<<dim3(32, 32, 4), dim3(32, 8)>>>(Wq, Wk, Wv, Wo);

    dim3 qkv_grid(CDIM / 128, MDIM / 128, 3);
    qkv_gemm_kernel<<<qkv_grid, 256, GEMM_SMEM>>>();

    dim3 attn_grid(T_SEQ / 128, N_H, 2);
    flash_tf32_kernel<<<attn_grid, 256, FLASH_SMEM_BYTES>>>();

    dim3 out_grid(CDIM / 128, MDIM / 128);
    out_gemm_kernel<<<out_grid, 256, GEMM_SMEM>>>(bo, out);
}

// round 9
// speedup vs baseline: 2.0227x; 1.8445x over previous
#include <cuda_runtime.h>
#include <cuda_fp16.h>
#include <math.h>

#define MDIM 4096
#define CDIM 1024
#define T_SEQ 2048
#define N_H 16
#define D_HEAD 64

typedef unsigned int u32;

// Scratch (device globals; fp16 packed 2-per-u32)
__device__ u32 g_xh[MDIM * CDIM / 2];                 // x fp16 [m][k]
__device__ u32 g_wh[4][CDIM * CDIM / 2];              // W^T fp16 [n][k]
__device__ u32 g_q[MDIM * CDIM / 2];                  // fp16, pre-scaled 0.125
__device__ u32 g_k[MDIM * CDIM / 2];                  // fp16
__device__ u32 g_vt[2 * N_H * D_HEAD * T_SEQ / 2];    // fp16 [b,h,d,t]
__device__ u32 g_y[MDIM * CDIM / 2];                  // fp16 [m][k]

// ---------------------------------------------------------------------------
// helpers
// ---------------------------------------------------------------------------
__device__ __forceinline__ u32 pk2(float lo, float hi) {
    __half2 h = __floats2half2_rn(lo, hi);
    return *(u32*)&h;
}

__device__ __forceinline__ void mma16(float* d, const u32* a, const u32* b) {
    asm volatile(
        "mma.sync.aligned.m16n8k16.row.col.f32.f16.f16.f32 "
        "{%0,%1,%2,%3}, {%4,%5,%6,%7}, {%8,%9}, {%0,%1,%2,%3};"
        : "+f"(d[0]), "+f"(d[1]), "+f"(d[2]), "+f"(d[3])
        : "r"(a[0]), "r"(a[1]), "r"(a[2]), "r"(a[3]), "r"(b[0]), "r"(b[1]));
}

__device__ __forceinline__ void ldsm4(u32& r0, u32& r1, u32& r2, u32& r3, u32 addr) {
    asm volatile("ldmatrix.sync.aligned.m8n8.x4.shared.b16 {%0,%1,%2,%3}, [%4];"
                 : "=r"(r0), "=r"(r1), "=r"(r2), "=r"(r3) : "r"(addr));
}

__device__ __forceinline__ void cp16(u32 dst, const void* src) {
    asm volatile("cp.async.cg.shared.global [%0], [%1], 16;" :: "r"(dst), "l"(src));
}
#define CP_COMMIT() asm volatile("cp.async.commit_group;")
#define CP_WAIT(n)  asm volatile("cp.async.wait_group %0;" :: "n"(n))

// ---------------------------------------------------------------------------
// prep: x -> fp16 [m][k]; W -> transposed [n][k] fp16
// ---------------------------------------------------------------------------
__global__ __launch_bounds__(256) void prep_x_kernel(const float* __restrict__ x)
{
    const float4* src = (const float4*)x;
    uint2* dst = (uint2*)g_xh;
    const int n4 = MDIM * CDIM / 4;
    for (int i = blockIdx.x * blockDim.x + threadIdx.x; i < n4;
         i += gridDim.x * blockDim.x) {
        float4 v = src[i];
        uint2 o;
        o.x = pk2(v.x, v.y);
        o.y = pk2(v.z, v.w);
        dst[i] = o;
    }
}

__global__ __launch_bounds__(256) void prep_w_kernel(const float* __restrict__ Wq,
                                                     const float* __restrict__ Wk,
                                                     const float* __restrict__ Wv,
                                                     const float* __restrict__ Wo)
{
    const int z = blockIdx.z;
    const float* W = (z == 0) ? Wq : (z == 1) ? Wk : (z == 2) ? Wv : Wo;
    __half* D = (__half*)g_wh[z];
    __shared__ float t[32][33];
    const int n0 = blockIdx.x * 32, k0 = blockIdx.y * 32;
    const int tx = threadIdx.x, ty = threadIdx.y;  // 32 x 8
#pragma unroll
    for (int i = 0; i < 32; i += 8)
        t[ty + i][tx] = W[(size_t)(k0 + ty + i) * CDIM + n0 + tx];
    __syncthreads();
#pragma unroll
    for (int i = 0; i < 32; i += 8)
        D[(size_t)(n0 + ty + i) * CDIM + k0 + tx] = __float2half_rn(t[tx][ty + i]);
}

// ---------------------------------------------------------------------------
// fp16 GEMM: C[4096,1024] = A[m][k] @ Bt[n][k]^T (fp16 in, fp32 accum).
// R4-proven skeleton: reg-staged LDG, ping-pong smem, single sync per k-tile.
// 128x128 tile, ktile 32 fp16, 256 thr (8 warps 4x2, warp tile 32x64).
// smem rows pitch 80 B (40 fp16); all fragments via ldmatrix.x4 (b16).
// OUT_MODE 0: float+bias; 1: fp16*oscale; 2: V-transposed fp16 scatter.
// ---------------------------------------------------------------------------
#define PITCH_B 80
#define PITCH_U 20
#define AS_SZ (128 * PITCH_U)               // 2560 u32
#define GEMM_SMEM (4 * AS_SZ * 4)           // 40960 B

template <int OUT_MODE>
__device__ __forceinline__ void gemm_core(const u32* __restrict__ A,
                                          const u32* __restrict__ Bt,
                                          const float* __restrict__ bias,
                                          void* __restrict__ Cv, float oscale)
{
    extern __shared__ u32 sm[];
    u32* As = sm;                 // [2][AS_SZ]
    u32* Bs = sm + 2 * AS_SZ;     // [2][AS_SZ]
    const u32 smbase = (u32)__cvta_generic_to_shared(sm);

    const int tid = threadIdx.x;
    const int lane = tid & 31;
    const int warp = tid >> 5;
    const int wm = warp >> 1;
    const int wn = warp & 1;
    const int g = lane >> 2;
    const int t = lane & 3;
    const int l16 = lane & 15;
    const int lhi = lane & 16;    // 0 or 16 (byte offset)

    const int row0 = blockIdx.y * 128;
    const int col0 = blockIdx.x * 128;

    // loader: row = tid>>1, half-row (8 u32 = 16 fp16) per thread
    const int l_row = tid >> 1;
    const int l_h = tid & 1;
    const u32* Ag = A + (size_t)(row0 + l_row) * 512 + l_h * 8;
    const u32* Bg = Bt + (size_t)(col0 + l_row) * 512 + l_h * 8;

    // ldmatrix byte bases within a buffer
    const u32 a_f0 = (u32)((wm * 32 + l16) * PITCH_B + lhi);
    const u32 b_f0 = (u32)((wn * 64 + l16) * PITCH_B + lhi);

    uint4 ar[2], br[2];

    float acc[2][8][4];
#pragma unroll
    for (int mt = 0; mt < 2; mt++)
#pragma unroll
        for (int nt = 0; nt < 8; nt++)
#pragma unroll
            for (int i = 0; i < 4; i++) acc[mt][nt][i] = 0.f;

    // prologue: tile 0
#pragma unroll
    for (int i = 0; i < 2; i++) {
        ar[i] = *(const uint4*)(Ag + 4 * i);
        br[i] = *(const uint4*)(Bg + 4 * i);
    }
    {
        u32* ap = As + l_row * PITCH_U + l_h * 8;
        u32* bp = Bs + l_row * PITCH_U + l_h * 8;
#pragma unroll
        for (int i = 0; i < 2; i++) {
            *(uint4*)(ap + 4 * i) = ar[i];
            *(uint4*)(bp + 4 * i) = br[i];
        }
    }
    __syncthreads();

    for (int kt = 0; kt < 32; kt++) {
        const int cur = kt & 1;
        if (kt < 31) {
            const int k0 = (kt + 1) * 16;   // u32 units (32 fp16)
#pragma unroll
            for (int i = 0; i < 2; i++) {
                ar[i] = *(const uint4*)(Ag + k0 + 4 * i);
                br[i] = *(const uint4*)(Bg + k0 + 4 * i);
            }
        }
        const u32 abase = smbase + (u32)(cur * AS_SZ) * 4 + a_f0;
        const u32 bbase = smbase + (u32)((2 + cur) * AS_SZ) * 4 + b_f0;
#pragma unroll
        for (int kk = 0; kk < 2; kk++) {
            u32 af[2][4];
#pragma unroll
            for (int mt = 0; mt < 2; mt++) {
                u32 r0, r1, r2, r3;
                ldsm4(r0, r1, r2, r3, abase + (u32)(mt * 16 * PITCH_B + kk * 32));
                af[mt][0] = r0; af[mt][1] = r1; af[mt][2] = r2; af[mt][3] = r3;
            }
            u32 bf[8][2];
#pragma unroll
            for (int ntp = 0; ntp < 4; ntp++) {
                u32 r0, r1, r2, r3;
                ldsm4(r0, r1, r2, r3, bbase + (u32)(ntp * 16 * PITCH_B + kk * 32));
                bf[2 * ntp][0] = r0;     bf[2 * ntp][1] = r2;
                bf[2 * ntp + 1][0] = r1; bf[2 * ntp + 1][1] = r3;
            }
#pragma unroll
            for (int nt = 0; nt < 8; nt++)
#pragma unroll
                for (int mt = 0; mt < 2; mt++)
                    mma16(acc[mt][nt], af[mt], bf[nt]);
        }
        if (kt < 31) {
            const int nbuf = (kt + 1) & 1;
            u32* ap = As + nbuf * AS_SZ + l_row * PITCH_U + l_h * 8;
            u32* bp = Bs + nbuf * AS_SZ + l_row * PITCH_U + l_h * 8;
#pragma unroll
            for (int i = 0; i < 2; i++) {
                *(uint4*)(ap + 4 * i) = ar[i];
                *(uint4*)(bp + 4 * i) = br[i];
            }
            __syncthreads();
        }
    }

    // epilogue
#pragma unroll
    for (int mt = 0; mt < 2; mt++) {
#pragma unroll
        for (int nt = 0; nt < 8; nt++) {
            const int r = row0 + wm * 32 + mt * 16 + g;
            const int c = col0 + wn * 64 + nt * 8 + t * 2;
            if (OUT_MODE == 0) {
                float* C = (float*)Cv;
                const float b0 = bias[c], b1 = bias[c + 1];
                *(float2*)(C + (size_t)r * CDIM + c) =
                    make_float2(acc[mt][nt][0] + b0, acc[mt][nt][1] + b1);
                *(float2*)(C + (size_t)(r + 8) * CDIM + c) =
                    make_float2(acc[mt][nt][2] + b0, acc[mt][nt][3] + b1);
            } else if (OUT_MODE == 1) {
                u32* C = (u32*)Cv;
                C[(size_t)r * 512 + (c >> 1)] =
                    pk2(acc[mt][nt][0] * oscale, acc[mt][nt][1] * oscale);
                C[(size_t)(r + 8) * 512 + (c >> 1)] =
                    pk2(acc[mt][nt][2] * oscale, acc[mt][nt][3] * oscale);
            } else {
                // V transposed: fp16 scatter into [b,h,d,t]
                __half* C = (__half*)Cv;
                const int bb = r >> 11;
                const int tt = r & 2047;
                const int hh = c >> 6;
                const int dd = c & 63;
                __half* base = C + (size_t)((bb * N_H + hh) * D_HEAD + dd) * T_SEQ;
                base[tt] = __float2half_rn(acc[mt][nt][0]);
                base[T_SEQ + tt] = __float2half_rn(acc[mt][nt][1]);
                base[tt + 8] = __float2half_rn(acc[mt][nt][2]);
                base[T_SEQ + tt + 8] = __float2half_rn(acc[mt][nt][3]);
            }
        }
    }
}

__global__ __launch_bounds__(256) void qkv_gemm_kernel()
{
    const int z = blockIdx.z;
    if (z == 0) gemm_core<1>(g_xh, g_wh[0], nullptr, g_q, 0.125f);
    else if (z == 1) gemm_core<1>(g_xh, g_wh[1], nullptr, g_k, 1.0f);
    else gemm_core<2>(g_xh, g_wh[2], nullptr, g_vt, 1.0f);
}

__global__ __launch_bounds__(256) void out_gemm_kernel(const float* __restrict__ bo,
                                                       float* __restrict__ out)
{
    gemm_core<0>(g_y, g_wh[3], bo, out, 1.0f);
}

// ---------------------------------------------------------------------------
// Flash attention, fp16 mma, causal. 256 thr (8 warps x 16 q-rows).
// KV tile 64, 2-stage cp.async. K [kv][d], Vt [d][t] fp16, pitch 144 B.
// grid: (T/128, H, B), reversed x order.
// ---------------------------------------------------------------------------
#define FPI_B 144
#define FPI_U 36
#define FKV_SZ (64 * FPI_U)    // 2304 u32
#define FP_SZ (16 * FPI_U)     // 576 u32
#define VT_OFF (2 * FKV_SZ)
#define PS_OFF (4 * FKV_SZ)
#define FLASH_SMEM_BYTES ((4 * FKV_SZ + 8 * FP_SZ) * 4)   // 55296 B

__device__ __forceinline__ void flash_issue(u32 smbase, const u32* Kg, const u32* Vtg,
                                            int j0, int buf, int tid)
{
    const int r = tid >> 2;             // K row (kv) / Vt row (d)
    const int q4 = tid & 3;
    const u32* ks = Kg + (size_t)(j0 + r) * 512 + q4 * 8;
    const u32* vs = Vtg + (size_t)r * 1024 + (j0 >> 1) + q4 * 8;
    const u32 kd = smbase + (u32)(buf * FKV_SZ * 4 + r * FPI_B + q4 * 32);
    const u32 vd = smbase + (u32)((VT_OFF + buf * FKV_SZ) * 4 + r * FPI_B + q4 * 32);
#pragma unroll
    for (int i = 0; i < 2; i++) {
        cp16(kd + 16 * i, ks + 4 * i);
        cp16(vd + 16 * i, vs + 4 * i);
    }
}

__global__ __launch_bounds__(256) void flash_fp16_kernel()
{
    extern __shared__ u32 sm[];
    const u32 smbase = (u32)__cvta_generic_to_shared(sm);

    const int tid = threadIdx.x;
    const int lane = tid & 31;
    const int warp = tid >> 5;
    const int g = lane >> 2;
    const int t4 = lane & 3;
    const int l16 = lane & 15;
    const int lhi = lane & 16;
    const int b = blockIdx.z;
    const int h = blockIdx.y;
    const int qb = gridDim.x - 1 - blockIdx.x;   // heavy blocks first
    const int q0 = qb * 128;
    const int qw = q0 + warp * 16;

    const u32* Kg = g_k + (size_t)(b * T_SEQ) * 512 + h * 32;
    const u32* Vtg = g_vt + (size_t)((b * N_H + h) * D_HEAD) * 1024;

    // Q fragments (fp16 pairs, pre-scaled)
    const u32* Qg = g_q + (size_t)(b * T_SEQ + qw) * 512 + h * 32;
    u32 qa[4][4];
#pragma unroll
    for (int kc = 0; kc < 4; kc++) {
        qa[kc][0] = Qg[(size_t)g * 512 + kc * 8 + t4];
        qa[kc][1] = Qg[(size_t)(g + 8) * 512 + kc * 8 + t4];
        qa[kc][2] = Qg[(size_t)g * 512 + kc * 8 + t4 + 4];
        qa[kc][3] = Qg[(size_t)(g + 8) * 512 + kc * 8 + t4 + 4];
    }

    float o[8][4];
#pragma unroll
    for (int nt = 0; nt < 8; nt++)
#pragma unroll
        for (int i = 0; i < 4; i++) o[nt][i] = 0.f;
    float m0 = -INFINITY, m1 = -INFINITY, l0 = 0.f, l1 = 0.f;

    const int ntiles = 2 * (qb + 1);
    const u32 p_off = (u32)(PS_OFF + warp * FP_SZ);
    u32* Pw = sm + p_off;

    flash_issue(smbase, Kg, Vtg, 0, 0, tid);
    CP_COMMIT();

#pragma unroll 1
    for (int tile = 0; tile < ntiles; tile++) {
        const int j0 = tile * 64;
        const int buf = tile & 1;
        if (tile + 1 < ntiles)
            flash_issue(smbase, Kg, Vtg, j0 + 64, (tile + 1) & 1, tid);
        CP_COMMIT();
        CP_WAIT(1);
        __syncthreads();

        if (j0 <= qw + 15) {
            // S = Q K^T
            float s[8][4];
#pragma unroll
            for (int nt = 0; nt < 8; nt++)
#pragma unroll
                for (int i = 0; i < 4; i++) s[nt][i] = 0.f;

            const u32 kbase = smbase + (u32)(buf * FKV_SZ * 4 + l16 * FPI_B + lhi);
#pragma unroll
            for (int kc = 0; kc < 4; kc++) {
                u32 bf[8][2];
#pragma unroll
                for (int ntp = 0; ntp < 4; ntp++) {
                    u32 r0, r1, r2, r3;
                    ldsm4(r0, r1, r2, r3, kbase + (u32)(ntp * 16 * FPI_B + kc * 32));
                    bf[2 * ntp][0] = r0;     bf[2 * ntp][1] = r2;
                    bf[2 * ntp + 1][0] = r1; bf[2 * ntp + 1][1] = r3;
                }
#pragma unroll
                for (int nt = 0; nt < 8; nt++)
                    mma16(s[nt], qa[kc], bf[nt]);
            }

            // causal mask (partial tiles only)
            if (j0 + 63 > qw) {
#pragma unroll
                for (int nt = 0; nt < 8; nt++) {
                    const int cb = j0 + nt * 8 + 2 * t4;
                    if (cb     > qw + g)     s[nt][0] = -INFINITY;
                    if (cb + 1 > qw + g)     s[nt][1] = -INFINITY;
                    if (cb     > qw + g + 8) s[nt][2] = -INFINITY;
                    if (cb + 1 > qw + g + 8) s[nt][3] = -INFINITY;
                }
            }

            // online softmax (rows g, g+8)
            float mx0 = -INFINITY, mx1 = -INFINITY;
#pragma unroll
            for (int nt = 0; nt < 8; nt++) {
                mx0 = fmaxf(mx0, fmaxf(s[nt][0], s[nt][1]));
                mx1 = fmaxf(mx1, fmaxf(s[nt][2], s[nt][3]));
            }
            mx0 = fmaxf(mx0, __shfl_xor_sync(0xffffffffu, mx0, 1));
            mx0 = fmaxf(mx0, __shfl_xor_sync(0xffffffffu, mx0, 2));
            mx1 = fmaxf(mx1, __shfl_xor_sync(0xffffffffu, mx1, 1));
            mx1 = fmaxf(mx1, __shfl_xor_sync(0xffffffffu, mx1, 2));

            const float mn0 = fmaxf(m0, mx0);
            const float mn1 = fmaxf(m1, mx1);
            const float cr0 = __expf(m0 - mn0);
            const float cr1 = __expf(m1 - mn1);
            float sum0 = 0.f, sum1 = 0.f;
#pragma unroll
            for (int nt = 0; nt < 8; nt++) {
                s[nt][0] = __expf(s[nt][0] - mn0);
                s[nt][1] = __expf(s[nt][1] - mn0);
                s[nt][2] = __expf(s[nt][2] - mn1);
                s[nt][3] = __expf(s[nt][3] - mn1);
                sum0 += s[nt][0] + s[nt][1];
                sum1 += s[nt][2] + s[nt][3];
            }
            sum0 += __shfl_xor_sync(0xffffffffu, sum0, 1);
            sum0 += __shfl_xor_sync(0xffffffffu, sum0, 2);
            sum1 += __shfl_xor_sync(0xffffffffu, sum1, 1);
            sum1 += __shfl_xor_sync(0xffffffffu, sum1, 2);
            l0 = l0 * cr0 + sum0;
            l1 = l1 * cr1 + sum1;
            m0 = mn0;
            m1 = mn1;
#pragma unroll
            for (int nt = 0; nt < 8; nt++) {
                o[nt][0] *= cr0;
                o[nt][1] *= cr0;
                o[nt][2] *= cr1;
                o[nt][3] *= cr1;
            }

            // stage P (fp16) into warp-private smem
#pragma unroll
            for (int nt = 0; nt < 8; nt++) {
                Pw[g * FPI_U + nt * 4 + t4] = pk2(s[nt][0], s[nt][1]);
                Pw[(g + 8) * FPI_U + nt * 4 + t4] = pk2(s[nt][2], s[nt][3]);
            }
            __syncwarp();

            // O += P V
            const u32 pbase = smbase + (u32)(p_off * 4 + l16 * FPI_B + lhi);
            const u32 vbase = smbase +
                (u32)((VT_OFF + buf * FKV_SZ) * 4 + l16 * FPI_B + lhi);
#pragma unroll
            for (int kc = 0; kc < 4; kc++) {
                u32 af[4];
                ldsm4(af[0], af[1], af[2], af[3], pbase + (u32)(kc * 32));
                u32 bf[8][2];
#pragma unroll
                for (int ntp = 0; ntp < 4; ntp++) {
                    u32 r0, r1, r2, r3;
                    ldsm4(r0, r1, r2, r3, vbase + (u32)(ntp * 16 * FPI_B + kc * 32));
                    bf[2 * ntp][0] = r0;     bf[2 * ntp][1] = r2;
                    bf[2 * ntp + 1][0] = r1; bf[2 * ntp + 1][1] = r3;
                }
#pragma unroll
                for (int nt = 0; nt < 8; nt++)
                    mma16(o[nt], af, bf[nt]);
            }
            __syncwarp();
        }
        __syncthreads();
    }

    // normalize + write fp16
    const float inv0 = 1.f / l0;
    const float inv1 = 1.f / l1;
    u32* Yg = g_y + (size_t)(b * T_SEQ + qw) * 512 + h * 32;
#pragma unroll
    for (int nt = 0; nt < 8; nt++) {
        Yg[(size_t)g * 512 + nt * 4 + t4] = pk2(o[nt][0] * inv0, o[nt][1] * inv0);
        Yg[(size_t)(g + 8) * 512 + nt * 4 + t4] = pk2(o[nt][2] * inv1, o[nt][3] * inv1);
    }
}

// ---------------------------------------------------------------------------
extern "C" void kernel_launch(void* const* d_in, const int* in_sizes, int n_in,
                              void* d_out, int out_size)
{
    const float* x  = (const float*)d_in[0];
    const float* Wq = (const float*)d_in[1];
    const float* Wk = (const float*)d_in[2];
    const float* Wv = (const float*)d_in[3];
    const float* Wo = (const float*)d_in[4];
    const float* bo = (const float*)d_in[5];
    float* out = (float*)d_out;
    (void)in_sizes; (void)n_in; (void)out_size;

    cudaFuncSetAttribute(qkv_gemm_kernel, cudaFuncAttributeMaxDynamicSharedMemorySize, GEMM_SMEM);
    cudaFuncSetAttribute(out_gemm_kernel, cudaFuncAttributeMaxDynamicSharedMemorySize, GEMM_SMEM);
    cudaFuncSetAttribute(flash_fp16_kernel, cudaFuncAttributeMaxDynamicSharedMemorySize, FLASH_SMEM_BYTES);

    prep_x_kernel<<<1024, 256>>>(x);
    prep_w_kernel<<<dim3(32, 32, 4), dim3(32, 8)>>>(Wq, Wk, Wv, Wo);

    dim3 qkv_grid(CDIM / 128, MDIM / 128, 3);
    qkv_gemm_kernel<<<qkv_grid, 256, GEMM_SMEM>>>();

    dim3 attn_grid(T_SEQ / 128, N_H, 2);
    flash_fp16_kernel<<<attn_grid, 256, FLASH_SMEM_BYTES>>>();

    dim3 out_grid(CDIM / 128, MDIM / 128);
    out_gemm_kernel<<<out_grid, 256, GEMM_SMEM>>>(bo, out);
}

// round 10
// speedup vs baseline: 2.1395x; 1.0578x over previous
#include <cuda_runtime.h>
#include <cuda_fp16.h>
#include <math.h>

#define MDIM 4096
#define CDIM 1024
#define T_SEQ 2048
#define N_H 16
#define D_HEAD 64

typedef unsigned int u32;

// Scratch (device globals; fp16 packed 2-per-u32)
__device__ u32 g_xh[MDIM * CDIM / 2];                 // x fp16 [m][k]
__device__ u32 g_wh[4][CDIM * CDIM / 2];              // W^T fp16 [n][k]
__device__ u32 g_q[MDIM * CDIM / 2];                  // fp16, pre-scaled 0.125*log2e
__device__ u32 g_k[MDIM * CDIM / 2];                  // fp16
__device__ u32 g_vt[2 * N_H * D_HEAD * T_SEQ / 2];    // fp16 [b,h,d,t]
__device__ u32 g_y[MDIM * CDIM / 2];                  // fp16 [m][k]

// ---------------------------------------------------------------------------
// helpers
// ---------------------------------------------------------------------------
__device__ __forceinline__ u32 pk2(float lo, float hi) {
    __half2 h = __floats2half2_rn(lo, hi);
    return *(u32*)&h;
}

__device__ __forceinline__ float ex2(float x) {
    float r;
    asm("ex2.approx.ftz.f32 %0, %1;" : "=f"(r) : "f"(x));
    return r;
}

__device__ __forceinline__ void mma16(float* d, const u32* a, const u32* b) {
    asm volatile(
        "mma.sync.aligned.m16n8k16.row.col.f32.f16.f16.f32 "
        "{%0,%1,%2,%3}, {%4,%5,%6,%7}, {%8,%9}, {%0,%1,%2,%3};"
        : "+f"(d[0]), "+f"(d[1]), "+f"(d[2]), "+f"(d[3])
        : "r"(a[0]), "r"(a[1]), "r"(a[2]), "r"(a[3]), "r"(b[0]), "r"(b[1]));
}

__device__ __forceinline__ void ldsm4(u32& r0, u32& r1, u32& r2, u32& r3, u32 addr) {
    asm volatile("ldmatrix.sync.aligned.m8n8.x4.shared.b16 {%0,%1,%2,%3}, [%4];"
                 : "=r"(r0), "=r"(r1), "=r"(r2), "=r"(r3) : "r"(addr));
}

__device__ __forceinline__ void cp16(u32 dst, const void* src) {
    asm volatile("cp.async.cg.shared.global [%0], [%1], 16;" :: "r"(dst), "l"(src));
}
#define CP_COMMIT() asm volatile("cp.async.commit_group;")
#define CP_WAIT(n)  asm volatile("cp.async.wait_group %0;" :: "n"(n))

// ---------------------------------------------------------------------------
// prep: x -> fp16 [m][k]; W -> transposed [n][k] fp16
// ---------------------------------------------------------------------------
__global__ __launch_bounds__(256) void prep_x_kernel(const float* __restrict__ x)
{
    const float4* src = (const float4*)x;
    uint2* dst = (uint2*)g_xh;
    const int n4 = MDIM * CDIM / 4;
    for (int i = blockIdx.x * blockDim.x + threadIdx.x; i < n4;
         i += gridDim.x * blockDim.x) {
        float4 v = src[i];
        uint2 o;
        o.x = pk2(v.x, v.y);
        o.y = pk2(v.z, v.w);
        dst[i] = o;
    }
}

__global__ __launch_bounds__(256) void prep_w_kernel(const float* __restrict__ Wq,
                                                     const float* __restrict__ Wk,
                                                     const float* __restrict__ Wv,
                                                     const float* __restrict__ Wo)
{
    const int z = blockIdx.z;
    const float* W = (z == 0) ? Wq : (z == 1) ? Wk : (z == 2) ? Wv : Wo;
    __half* D = (__half*)g_wh[z];
    __shared__ float t[32][33];
    const int n0 = blockIdx.x * 32, k0 = blockIdx.y * 32;
    const int tx = threadIdx.x, ty = threadIdx.y;  // 32 x 8
#pragma unroll
    for (int i = 0; i < 32; i += 8)
        t[ty + i][tx] = W[(size_t)(k0 + ty + i) * CDIM + n0 + tx];
    __syncthreads();
#pragma unroll
    for (int i = 0; i < 32; i += 8)
        D[(size_t)(n0 + ty + i) * CDIM + k0 + tx] = __float2half_rn(t[tx][ty + i]);
}

// ---------------------------------------------------------------------------
// fp16 GEMM (R9-proven): C[4096,1024] = A[m][k] @ Bt[n][k]^T.
// ---------------------------------------------------------------------------
#define PITCH_B 80
#define PITCH_U 20
#define AS_SZ (128 * PITCH_U)               // 2560 u32
#define GEMM_SMEM (4 * AS_SZ * 4)           // 40960 B

template <int OUT_MODE>
__device__ __forceinline__ void gemm_core(const u32* __restrict__ A,
                                          const u32* __restrict__ Bt,
                                          const float* __restrict__ bias,
                                          void* __restrict__ Cv, float oscale)
{
    extern __shared__ u32 sm[];
    u32* As = sm;
    u32* Bs = sm + 2 * AS_SZ;
    const u32 smbase = (u32)__cvta_generic_to_shared(sm);

    const int tid = threadIdx.x;
    const int lane = tid & 31;
    const int warp = tid >> 5;
    const int wm = warp >> 1;
    const int wn = warp & 1;
    const int g = lane >> 2;
    const int t = lane & 3;
    const int l16 = lane & 15;
    const int lhi = lane & 16;

    const int row0 = blockIdx.y * 128;
    const int col0 = blockIdx.x * 128;

    const int l_row = tid >> 1;
    const int l_h = tid & 1;
    const u32* Ag = A + (size_t)(row0 + l_row) * 512 + l_h * 8;
    const u32* Bg = Bt + (size_t)(col0 + l_row) * 512 + l_h * 8;

    const u32 a_f0 = (u32)((wm * 32 + l16) * PITCH_B + lhi);
    const u32 b_f0 = (u32)((wn * 64 + l16) * PITCH_B + lhi);

    uint4 ar[2], br[2];

    float acc[2][8][4];
#pragma unroll
    for (int mt = 0; mt < 2; mt++)
#pragma unroll
        for (int nt = 0; nt < 8; nt++)
#pragma unroll
            for (int i = 0; i < 4; i++) acc[mt][nt][i] = 0.f;

#pragma unroll
    for (int i = 0; i < 2; i++) {
        ar[i] = *(const uint4*)(Ag + 4 * i);
        br[i] = *(const uint4*)(Bg + 4 * i);
    }
    {
        u32* ap = As + l_row * PITCH_U + l_h * 8;
        u32* bp = Bs + l_row * PITCH_U + l_h * 8;
#pragma unroll
        for (int i = 0; i < 2; i++) {
            *(uint4*)(ap + 4 * i) = ar[i];
            *(uint4*)(bp + 4 * i) = br[i];
        }
    }
    __syncthreads();

    for (int kt = 0; kt < 32; kt++) {
        const int cur = kt & 1;
        if (kt < 31) {
            const int k0 = (kt + 1) * 16;
#pragma unroll
            for (int i = 0; i < 2; i++) {
                ar[i] = *(const uint4*)(Ag + k0 + 4 * i);
                br[i] = *(const uint4*)(Bg + k0 + 4 * i);
            }
        }
        const u32 abase = smbase + (u32)(cur * AS_SZ) * 4 + a_f0;
        const u32 bbase = smbase + (u32)((2 + cur) * AS_SZ) * 4 + b_f0;
#pragma unroll
        for (int kk = 0; kk < 2; kk++) {
            u32 af[2][4];
#pragma unroll
            for (int mt = 0; mt < 2; mt++) {
                u32 r0, r1, r2, r3;
                ldsm4(r0, r1, r2, r3, abase + (u32)(mt * 16 * PITCH_B + kk * 32));
                af[mt][0] = r0; af[mt][1] = r1; af[mt][2] = r2; af[mt][3] = r3;
            }
            u32 bf[8][2];
#pragma unroll
            for (int ntp = 0; ntp < 4; ntp++) {
                u32 r0, r1, r2, r3;
                ldsm4(r0, r1, r2, r3, bbase + (u32)(ntp * 16 * PITCH_B + kk * 32));
                bf[2 * ntp][0] = r0;     bf[2 * ntp][1] = r2;
                bf[2 * ntp + 1][0] = r1; bf[2 * ntp + 1][1] = r3;
            }
#pragma unroll
            for (int nt = 0; nt < 8; nt++)
#pragma unroll
                for (int mt = 0; mt < 2; mt++)
                    mma16(acc[mt][nt], af[mt], bf[nt]);
        }
        if (kt < 31) {
            const int nbuf = (kt + 1) & 1;
            u32* ap = As + nbuf * AS_SZ + l_row * PITCH_U + l_h * 8;
            u32* bp = Bs + nbuf * AS_SZ + l_row * PITCH_U + l_h * 8;
#pragma unroll
            for (int i = 0; i < 2; i++) {
                *(uint4*)(ap + 4 * i) = ar[i];
                *(uint4*)(bp + 4 * i) = br[i];
            }
            __syncthreads();
        }
    }

#pragma unroll
    for (int mt = 0; mt < 2; mt++) {
#pragma unroll
        for (int nt = 0; nt < 8; nt++) {
            const int r = row0 + wm * 32 + mt * 16 + g;
            const int c = col0 + wn * 64 + nt * 8 + t * 2;
            if (OUT_MODE == 0) {
                float* C = (float*)Cv;
                const float b0 = bias[c], b1 = bias[c + 1];
                *(float2*)(C + (size_t)r * CDIM + c) =
                    make_float2(acc[mt][nt][0] + b0, acc[mt][nt][1] + b1);
                *(float2*)(C + (size_t)(r + 8) * CDIM + c) =
                    make_float2(acc[mt][nt][2] + b0, acc[mt][nt][3] + b1);
            } else if (OUT_MODE == 1) {
                u32* C = (u32*)Cv;
                C[(size_t)r * 512 + (c >> 1)] =
                    pk2(acc[mt][nt][0] * oscale, acc[mt][nt][1] * oscale);
                C[(size_t)(r + 8) * 512 + (c >> 1)] =
                    pk2(acc[mt][nt][2] * oscale, acc[mt][nt][3] * oscale);
            } else {
                __half* C = (__half*)Cv;
                const int bb = r >> 11;
                const int tt = r & 2047;
                const int hh = c >> 6;
                const int dd = c & 63;
                __half* base = C + (size_t)((bb * N_H + hh) * D_HEAD + dd) * T_SEQ;
                base[tt] = __float2half_rn(acc[mt][nt][0]);
                base[T_SEQ + tt] = __float2half_rn(acc[mt][nt][1]);
                base[tt + 8] = __float2half_rn(acc[mt][nt][2]);
                base[T_SEQ + tt + 8] = __float2half_rn(acc[mt][nt][3]);
            }
        }
    }
}

__global__ __launch_bounds__(256) void qkv_gemm_kernel()
{
    const int z = blockIdx.z;
    // Q pre-scaled by 0.125 * log2(e) -> softmax computed in log2 domain
    if (z == 0) gemm_core<1>(g_xh, g_wh[0], nullptr, g_q, 0.125f * 1.4426950408889634f);
    else if (z == 1) gemm_core<1>(g_xh, g_wh[1], nullptr, g_k, 1.0f);
    else gemm_core<2>(g_xh, g_wh[2], nullptr, g_vt, 1.0f);
}

__global__ __launch_bounds__(256) void out_gemm_kernel(const float* __restrict__ bo,
                                                       float* __restrict__ out)
{
    gemm_core<0>(g_y, g_wh[3], bo, out, 1.0f);
}

// ---------------------------------------------------------------------------
// Flash attention, fp16 mma, causal. 256 thr (8 warps x 16 q-rows).
// KV tile 64, 2-stage cp.async. P kept entirely in registers (S-accum layout
// == A-fragment layout for m16n8k16). Softmax in log2 domain (ex2.approx).
// grid: (T/128, H, B), reversed x order.
// ---------------------------------------------------------------------------
#define FPI_B 144
#define FPI_U 36
#define FKV_SZ (64 * FPI_U)    // 2304 u32
#define VT_OFF (2 * FKV_SZ)
#define FLASH_SMEM_BYTES (4 * FKV_SZ * 4)   // 36864 B

__device__ __forceinline__ void flash_issue(u32 smbase, const u32* Kg, const u32* Vtg,
                                            int j0, int buf, int tid)
{
    const int r = tid >> 2;             // K row (kv) / Vt row (d)
    const int q4 = tid & 3;
    const u32* ks = Kg + (size_t)(j0 + r) * 512 + q4 * 8;
    const u32* vs = Vtg + (size_t)r * 1024 + (j0 >> 1) + q4 * 8;
    const u32 kd = smbase + (u32)(buf * FKV_SZ * 4 + r * FPI_B + q4 * 32);
    const u32 vd = smbase + (u32)((VT_OFF + buf * FKV_SZ) * 4 + r * FPI_B + q4 * 32);
#pragma unroll
    for (int i = 0; i < 2; i++) {
        cp16(kd + 16 * i, ks + 4 * i);
        cp16(vd + 16 * i, vs + 4 * i);
    }
}

__global__ __launch_bounds__(256) void flash_fp16_kernel()
{
    extern __shared__ u32 sm[];
    const u32 smbase = (u32)__cvta_generic_to_shared(sm);

    const int tid = threadIdx.x;
    const int lane = tid & 31;
    const int warp = tid >> 5;
    const int g = lane >> 2;
    const int t4 = lane & 3;
    const int l16 = lane & 15;
    const int lhi = lane & 16;
    const int b = blockIdx.z;
    const int h = blockIdx.y;
    const int qb = gridDim.x - 1 - blockIdx.x;   // heavy blocks first
    const int q0 = qb * 128;
    const int qw = q0 + warp * 16;

    const u32* Kg = g_k + (size_t)(b * T_SEQ) * 512 + h * 32;
    const u32* Vtg = g_vt + (size_t)((b * N_H + h) * D_HEAD) * 1024;

    // Q fragments (fp16 pairs, pre-scaled by 0.125*log2e)
    const u32* Qg = g_q + (size_t)(b * T_SEQ + qw) * 512 + h * 32;
    u32 qa[4][4];
#pragma unroll
    for (int kc = 0; kc < 4; kc++) {
        qa[kc][0] = Qg[(size_t)g * 512 + kc * 8 + t4];
        qa[kc][1] = Qg[(size_t)(g + 8) * 512 + kc * 8 + t4];
        qa[kc][2] = Qg[(size_t)g * 512 + kc * 8 + t4 + 4];
        qa[kc][3] = Qg[(size_t)(g + 8) * 512 + kc * 8 + t4 + 4];
    }

    float o[8][4];
#pragma unroll
    for (int nt = 0; nt < 8; nt++)
#pragma unroll
        for (int i = 0; i < 4; i++) o[nt][i] = 0.f;
    float m0 = -INFINITY, m1 = -INFINITY, l0 = 0.f, l1 = 0.f;

    const int ntiles = 2 * (qb + 1);

    flash_issue(smbase, Kg, Vtg, 0, 0, tid);
    CP_COMMIT();

#pragma unroll 1
    for (int tile = 0; tile < ntiles; tile++) {
        const int j0 = tile * 64;
        const int buf = tile & 1;
        if (tile + 1 < ntiles)
            flash_issue(smbase, Kg, Vtg, j0 + 64, (tile + 1) & 1, tid);
        CP_COMMIT();
        CP_WAIT(1);
        __syncthreads();

        if (j0 <= qw + 15) {
            // S = Q K^T (log2-scaled)
            float s[8][4];
#pragma unroll
            for (int nt = 0; nt < 8; nt++)
#pragma unroll
                for (int i = 0; i < 4; i++) s[nt][i] = 0.f;

            const u32 kbase = smbase + (u32)(buf * FKV_SZ * 4 + l16 * FPI_B + lhi);
#pragma unroll
            for (int kc = 0; kc < 4; kc++) {
                u32 bf[8][2];
#pragma unroll
                for (int ntp = 0; ntp < 4; ntp++) {
                    u32 r0, r1, r2, r3;
                    ldsm4(r0, r1, r2, r3, kbase + (u32)(ntp * 16 * FPI_B + kc * 32));
                    bf[2 * ntp][0] = r0;     bf[2 * ntp][1] = r2;
                    bf[2 * ntp + 1][0] = r1; bf[2 * ntp + 1][1] = r3;
                }
#pragma unroll
                for (int nt = 0; nt < 8; nt++)
                    mma16(s[nt], qa[kc], bf[nt]);
            }

            // causal mask (partial tiles only)
            if (j0 + 63 > qw) {
#pragma unroll
                for (int nt = 0; nt < 8; nt++) {
                    const int cb = j0 + nt * 8 + 2 * t4;
                    if (cb     > qw + g)     s[nt][0] = -INFINITY;
                    if (cb + 1 > qw + g)     s[nt][1] = -INFINITY;
                    if (cb     > qw + g + 8) s[nt][2] = -INFINITY;
                    if (cb + 1 > qw + g + 8) s[nt][3] = -INFINITY;
                }
            }

            // online softmax in log2 domain (rows g, g+8)
            float mx0 = -INFINITY, mx1 = -INFINITY;
#pragma unroll
            for (int nt = 0; nt < 8; nt++) {
                mx0 = fmaxf(mx0, fmaxf(s[nt][0], s[nt][1]));
                mx1 = fmaxf(mx1, fmaxf(s[nt][2], s[nt][3]));
            }
            mx0 = fmaxf(mx0, __shfl_xor_sync(0xffffffffu, mx0, 1));
            mx0 = fmaxf(mx0, __shfl_xor_sync(0xffffffffu, mx0, 2));
            mx1 = fmaxf(mx1, __shfl_xor_sync(0xffffffffu, mx1, 1));
            mx1 = fmaxf(mx1, __shfl_xor_sync(0xffffffffu, mx1, 2));

            const float mn0 = fmaxf(m0, mx0);
            const float mn1 = fmaxf(m1, mx1);
            const float cr0 = ex2(m0 - mn0);
            const float cr1 = ex2(m1 - mn1);
            float sum0 = 0.f, sum1 = 0.f;
#pragma unroll
            for (int nt = 0; nt < 8; nt++) {
                s[nt][0] = ex2(s[nt][0] - mn0);
                s[nt][1] = ex2(s[nt][1] - mn0);
                s[nt][2] = ex2(s[nt][2] - mn1);
                s[nt][3] = ex2(s[nt][3] - mn1);
                sum0 += s[nt][0] + s[nt][1];
                sum1 += s[nt][2] + s[nt][3];
            }
            sum0 += __shfl_xor_sync(0xffffffffu, sum0, 1);
            sum0 += __shfl_xor_sync(0xffffffffu, sum0, 2);
            sum1 += __shfl_xor_sync(0xffffffffu, sum1, 1);
            sum1 += __shfl_xor_sync(0xffffffffu, sum1, 2);
            l0 = l0 * cr0 + sum0;
            l1 = l1 * cr1 + sum1;
            m0 = mn0;
            m1 = mn1;
#pragma unroll
            for (int nt = 0; nt < 8; nt++) {
                o[nt][0] *= cr0;
                o[nt][1] *= cr0;
                o[nt][2] *= cr1;
                o[nt][3] *= cr1;
            }

            // O += P V; P A-fragments built directly from S registers
            const u32 vbase = smbase +
                (u32)((VT_OFF + buf * FKV_SZ) * 4 + l16 * FPI_B + lhi);
#pragma unroll
            for (int kc = 0; kc < 4; kc++) {
                u32 af[4];
                af[0] = pk2(s[2 * kc][0], s[2 * kc][1]);          // row g,   cols 16kc+2t4
                af[1] = pk2(s[2 * kc][2], s[2 * kc][3]);          // row g+8, cols 16kc+2t4
                af[2] = pk2(s[2 * kc + 1][0], s[2 * kc + 1][1]);  // row g,   cols 16kc+8+2t4
                af[3] = pk2(s[2 * kc + 1][2], s[2 * kc + 1][3]);  // row g+8, cols 16kc+8+2t4
                u32 bf[8][2];
#pragma unroll
                for (int ntp = 0; ntp < 4; ntp++) {
                    u32 r0, r1, r2, r3;
                    ldsm4(r0, r1, r2, r3, vbase + (u32)(ntp * 16 * FPI_B + kc * 32));
                    bf[2 * ntp][0] = r0;     bf[2 * ntp][1] = r2;
                    bf[2 * ntp + 1][0] = r1; bf[2 * ntp + 1][1] = r3;
                }
#pragma unroll
                for (int nt = 0; nt < 8; nt++)
                    mma16(o[nt], af, bf[nt]);
            }
        }
        __syncthreads();
    }

    // normalize + write fp16
    const float inv0 = 1.f / l0;
    const float inv1 = 1.f / l1;
    u32* Yg = g_y + (size_t)(b * T_SEQ + qw) * 512 + h * 32;
#pragma unroll
    for (int nt = 0; nt < 8; nt++) {
        Yg[(size_t)g * 512 + nt * 4 + t4] = pk2(o[nt][0] * inv0, o[nt][1] * inv0);
        Yg[(size_t)(g + 8) * 512 + nt * 4 + t4] = pk2(o[nt][2] * inv1, o[nt][3] * inv1);
    }
}

// ---------------------------------------------------------------------------
extern "C" void kernel_launch(void* const* d_in, const int* in_sizes, int n_in,
                              void* d_out, int out_size)
{
    const float* x  = (const float*)d_in[0];
    const float* Wq = (const float*)d_in[1];
    const float* Wk = (const float*)d_in[2];
    const float* Wv = (const float*)d_in[3];
    const float* Wo = (const float*)d_in[4];
    const float* bo = (const float*)d_in[5];
    float* out = (float*)d_out;
    (void)in_sizes; (void)n_in; (void)out_size;

    cudaFuncSetAttribute(qkv_gemm_kernel, cudaFuncAttributeMaxDynamicSharedMemorySize, GEMM_SMEM);
    cudaFuncSetAttribute(out_gemm_kernel, cudaFuncAttributeMaxDynamicSharedMemorySize, GEMM_SMEM);
    cudaFuncSetAttribute(flash_fp16_kernel, cudaFuncAttributeMaxDynamicSharedMemorySize, FLASH_SMEM_BYTES);

    prep_x_kernel<<<1024, 256>>>(x);
    prep_w_kernel<<<dim3(32, 32, 4), dim3(32, 8)>>>(Wq, Wk, Wv, Wo);

    dim3 qkv_grid(CDIM / 128, MDIM / 128, 3);
    qkv_gemm_kernel<<<qkv_grid, 256, GEMM_SMEM>>>();

    dim3 attn_grid(T_SEQ / 128, N_H, 2);
    flash_fp16_kernel<<<attn_grid, 256, FLASH_SMEM_BYTES>>>();

    dim3 out_grid(CDIM / 128, MDIM / 128);
    out_gemm_kernel<<<out_grid, 256, GEMM_SMEM>>>(bo, out);
}